// round 11
// baseline (speedup 1.0000x reference)
#include <cuda_runtime.h>
#include <cuda_fp16.h>
#include <cstdint>

// Fixed problem shape
#define BB   8
#define CC   256
#define HH   64
#define WWD  64
#define OO   256
#define KKT  9
#define HWSZ 4096

#define TP   128         // pixel tile per CTA
#define NT   512         // 16 warps: 4 M-warps (o) x 4 N-warps (px)
#define NITER 18         // 2 c-chunks of 128 x 9 kpos (kpos innermost)

// ---- smem layout (bytes): taps 18432 + B 2x32768 = 83968 -> ~144KB left for L1 ----
#define SM_T    0
#define SM_B    18432
#define SMEM_TOTAL 83968

// Packed bilinear tap: 4 corner indices + 4 fp16 weights (mask-premultiplied)
struct __align__(16) Tap {
    unsigned short idx[4];
    __half2 w01;
    __half2 w23;
};

// ---- device scratch ----
// Weights pre-arranged in mma A-fragment order:
//   g_wf[jt][ks][otile][lane][reg]  (uint32 = half2), jt = chunk*9 + kpos
//   reg0: A[o=ot*16+(l>>2)     ][c=base+(l&3)*2]   reg1: row+8
//   reg2: A[row                ][c+8]              reg3: row+8, c+8
#define WF_PER_JT (8 * 16 * 32 * 4)          // 16384 uint32 per jt
__device__ __align__(16) uint32_t g_wf[18 * WF_PER_JT];
__device__ __align__(16) __half   g_xn[(size_t)BB * HWSZ * CC];   // NHWC fp16

// ---------------- prep kernels ----------------
__global__ void prep_wfrag(const float* __restrict__ w) {
    const int idx = blockIdx.x * 256 + threadIdx.x;     // one uint32 each
    const int reg   = idx & 3;
    const int lane  = (idx >> 2) & 31;
    const int otile = (idx >> 7) & 15;
    const int ks    = (idx >> 11) & 7;
    const int jt    = idx >> 14;
    if (jt >= 18) return;
    const int chunk = jt / KKT;
    const int kpos  = jt - chunk * KKT;
    const int o = otile * 16 + (lane >> 2) + (reg & 1) * 8;
    const int c = chunk * 128 + ks * 16 + (lane & 3) * 2 + (reg >> 1) * 8;
    const float v0 = w[((size_t)o * CC + c) * KKT + kpos];
    const float v1 = w[((size_t)o * CC + c + 1) * KKT + kpos];
    const __half2 h = __floats2half2_rn(v0, v1);
    g_wf[idx] = *(const uint32_t*)&h;
}

__global__ void prep_nhwc(const float* __restrict__ x) {
    __shared__ float tile[32][33];
    int bb = blockIdx.z, hw0 = blockIdx.x * 32, c0 = blockIdx.y * 32;
    int tx = threadIdx.x, ty = threadIdx.y;
    const float* src = x + (size_t)bb * CC * HWSZ;
    #pragma unroll
    for (int i = 0; i < 32; i += 8)
        tile[ty + i][tx] = src[(size_t)(c0 + ty + i) * HWSZ + hw0 + tx];
    __syncthreads();
    __half* dst = g_xn + (size_t)bb * HWSZ * CC;
    #pragma unroll
    for (int i = 0; i < 32; i += 8)
        dst[(size_t)(hw0 + ty + i) * CC + c0 + tx] = __float2half_rn(tile[tx][ty + i]);
}

// ---------------- helpers ----------------
__device__ __forceinline__ uint32_t s2u(const void* p) {
    uint32_t r;
    asm("{ .reg .u64 t; cvta.to.shared.u64 t, %1; cvt.u32.u64 %0, t; }" : "=r"(r) : "l"(p));
    return r;
}
__device__ __forceinline__ uint32_t sw128(uint32_t off) {
    return off ^ ((off >> 3) & 0x70);
}
__device__ __forceinline__ void ldsm_x4(uint32_t addr, uint32_t& r0, uint32_t& r1,
                                        uint32_t& r2, uint32_t& r3) {
    asm volatile("ldmatrix.sync.aligned.m8n8.x4.shared.b16 {%0,%1,%2,%3}, [%4];"
                 : "=r"(r0), "=r"(r1), "=r"(r2), "=r"(r3) : "r"(addr));
}
__device__ __forceinline__ void mma_fp16(float* d, const uint32_t* a, uint32_t b0, uint32_t b1) {
    asm volatile("mma.sync.aligned.m16n8k16.row.col.f32.f16.f16.f32 "
                 "{%0,%1,%2,%3}, {%4,%5,%6,%7}, {%8,%9}, {%0,%1,%2,%3};"
                 : "+f"(d[0]), "+f"(d[1]), "+f"(d[2]), "+f"(d[3])
                 : "r"(a[0]), "r"(a[1]), "r"(a[2]), "r"(a[3]), "r"(b0), "r"(b1));
}

extern __shared__ char smraw[];

__global__ __launch_bounds__(NT, 1)
void dcn_mma9_kernel(const float* __restrict__ offs,
                     const float* __restrict__ mask,
                     const float* __restrict__ bias,
                     float* __restrict__ out) {
    const int tid  = threadIdx.x;
    const int lane = tid & 31;
    const int wid  = tid >> 5;
    const int warpM = wid >> 2;        // 0..3 -> 64 o-rows
    const int warpN = wid & 3;         // 0..3 -> 32 px
    const int bb   = blockIdx.y;
    const int hw0  = blockIdx.x * TP;

    Tap* sT = (Tap*)(smraw + SM_T);
    const uint32_t uB = s2u(smraw + SM_B);

    // ---- taps: bilinear corner indices + mask-premultiplied fp16 weights ----
    for (int i = tid; i < KKT * TP; i += NT) {
        const int k  = i / TP;
        const int p  = i - k * TP;
        const int hw = hw0 + p;
        const int h  = hw >> 6;
        const int w  = hw & 63;

        const float oy = offs[((size_t)bb * 18 + k * 2 + 0) * HWSZ + hw];
        const float ox = offs[((size_t)bb * 18 + k * 2 + 1) * HWSZ + hw];
        const float m  = mask[((size_t)bb * KKT + k) * HWSZ + hw];

        const float py = (float)(h - 1 + k / 3) + oy;
        const float px = (float)(w - 1 + k % 3) + ox;
        const float fy = floorf(py), fx = floorf(px);
        const int y0 = (int)fy, x0 = (int)fx;
        const float ly = py - fy, lx = px - fx;
        const float hy = 1.0f - ly, hx = 1.0f - lx;

        const bool vy0 = (y0 >= 0) && (y0 < HH);
        const bool vy1 = (y0 + 1 >= 0) && (y0 + 1 < HH);
        const bool vx0 = (x0 >= 0) && (x0 < WWD);
        const bool vx1 = (x0 + 1 >= 0) && (x0 + 1 < WWD);
        const int cy0 = min(max(y0, 0), HH - 1);
        const int cy1 = min(max(y0 + 1, 0), HH - 1);
        const int cx0 = min(max(x0, 0), WWD - 1);
        const int cx1 = min(max(x0 + 1, 0), WWD - 1);

        Tap t;
        t.idx[0] = (unsigned short)(cy0 * WWD + cx0);
        t.idx[1] = (unsigned short)(cy0 * WWD + cx1);
        t.idx[2] = (unsigned short)(cy1 * WWD + cx0);
        t.idx[3] = (unsigned short)(cy1 * WWD + cx1);
        const float w0v = (vy0 && vx0) ? hy * hx * m : 0.0f;
        const float w1v = (vy0 && vx1) ? hy * lx * m : 0.0f;
        const float w2v = (vy1 && vx0) ? ly * hx * m : 0.0f;
        const float w3v = (vy1 && vx1) ? ly * lx * m : 0.0f;
        t.w01 = __floats2half2_rn(w0v, w1v);
        t.w23 = __floats2half2_rn(w2v, w3v);
        sT[i] = t;
    }

    const __half* __restrict__ xb = g_xn + (size_t)bb * HWSZ * CC;

    float acc[4][4][4];
    #pragma unroll
    for (int mf = 0; mf < 4; ++mf)
        #pragma unroll
        for (int nf = 0; nf < 4; ++nf)
            #pragma unroll
            for (int r = 0; r < 4; ++r) acc[mf][nf][r] = 0.0f;

    // Per-pixel gather pipeline: 2 slots x (4 corners uint2 + packed weights)
    uint2   g[2][4];
    __half2 wA[2], wB[2];
    auto loadP = [&](int jt, int p, int s) {
        const int kpos = jt % KKT;
        const int c0   = (jt / KKT) * 128;
        const __half* xc = xb + c0 + 4 * lane;
        const Tap t = sT[kpos * TP + wid * 8 + p];   // single LDS.128
        g[s][0] = *(const uint2*)(xc + (size_t)t.idx[0] * CC);
        g[s][1] = *(const uint2*)(xc + (size_t)t.idx[1] * CC);
        g[s][2] = *(const uint2*)(xc + (size_t)t.idx[2] * CC);
        g[s][3] = *(const uint2*)(xc + (size_t)t.idx[3] * CC);
        wA[s] = t.w01;
        wB[s] = t.w23;
    };
    auto storeP = [&](int p, int s, int buf) {
        char* Bb = smraw + SM_B + buf * 32768 + (lane >> 4) * 16384;
        const int pp = wid * 8 + p;
        const __half2 h0 = __low2half2(wA[s]);
        const __half2 h1 = __high2half2(wA[s]);
        const __half2 h2 = __low2half2(wB[s]);
        const __half2 h3 = __high2half2(wB[s]);
        __half2 vA = __hmul2(h0, *(__half2*)&g[s][0].x);
        vA = __hfma2(h1, *(__half2*)&g[s][1].x, vA);
        vA = __hfma2(h2, *(__half2*)&g[s][2].x, vA);
        vA = __hfma2(h3, *(__half2*)&g[s][3].x, vA);
        __half2 vBv = __hmul2(h0, *(__half2*)&g[s][0].y);
        vBv = __hfma2(h1, *(__half2*)&g[s][1].y, vBv);
        vBv = __hfma2(h2, *(__half2*)&g[s][2].y, vBv);
        vBv = __hfma2(h3, *(__half2*)&g[s][3].y, vBv);
        uint2 pk;
        pk.x = *(uint32_t*)&vA;
        pk.y = *(uint32_t*)&vBv;
        *(uint2*)(Bb + sw128((uint32_t)(pp * 128 + (lane & 15) * 8))) = pk;
    };
    auto mmaKS = [&](int jt, int ks, int buf) {
        const int half = ks >> 2;
        const uint32_t bbase = uB + buf * 32768 + half * 16384;
        // A fragments: direct coalesced LDG.128 from fragment-ordered weights
        const uint32_t* wf = g_wf + (size_t)jt * WF_PER_JT + (size_t)ks * (16 * 32 * 4);
        uint32_t a[4][4];
        #pragma unroll
        for (int mf = 0; mf < 4; ++mf) {
            const uint4 av = *(const uint4*)(wf + ((warpM * 4 + mf) * 32 + lane) * 4);
            a[mf][0] = av.x; a[mf][1] = av.y; a[mf][2] = av.z; a[mf][3] = av.w;
        }
        const int ksl = ks & 3;
        uint32_t bfr[4][2];
        #pragma unroll
        for (int pb = 0; pb < 2; ++pb) {
            const uint32_t off = (uint32_t)((warpN * 32 + pb * 16 + (lane & 15)) * 128
                                            + ksl * 32 + (lane >> 4) * 16);
            uint32_t r0, r1, r2, r3;
            ldsm_x4(bbase + sw128(off), r0, r1, r2, r3);
            bfr[pb * 2 + 0][0] = r0; bfr[pb * 2 + 0][1] = r2;
            bfr[pb * 2 + 1][0] = r1; bfr[pb * 2 + 1][1] = r3;
        }
        #pragma unroll
        for (int mf = 0; mf < 4; ++mf)
            #pragma unroll
            for (int nf = 0; nf < 4; ++nf)
                mma_fp16(acc[mf][nf], a[mf], bfr[nf][0], bfr[nf][1]);
    };

    __syncthreads();   // taps ready

    // ---- prologue: build iteration 0 into buffer 0 ----
    #pragma unroll
    for (int p = 0; p < 8; ++p) { loadP(0, p, p & 1); storeP(p, p & 1, 0); }
    __syncthreads();

    // ---- main loop: one sync per iter; build(it+1) woven into the 8 mmaKS of it ----
    for (int it = 0; it < NITER; ++it) {
        const int buf  = it & 1;
        const int nbuf = buf ^ 1;
        const bool more = (it + 1 < NITER);
        if (more) { loadP(it + 1, 0, 0); loadP(it + 1, 1, 1); }

        #pragma unroll
        for (int j = 0; j < 8; ++j) {
            mmaKS(it, j, buf);
            if (more) {
                storeP(j, j & 1, nbuf);
                if (j < 6) loadP(it + 1, j + 2, j & 1);
            }
        }
        __syncthreads();
    }

    // ---- epilogue: bias add + fp32 stores ----
    #pragma unroll
    for (int mf = 0; mf < 4; ++mf) {
        const int o0 = warpM * 64 + mf * 16 + (lane >> 2);
        const float bv0 = bias[o0];
        const float bv1 = bias[o0 + 8];
        #pragma unroll
        for (int nf = 0; nf < 4; ++nf) {
            const int p = hw0 + warpN * 32 + nf * 8 + (lane & 3) * 2;
            float* d0 = out + ((size_t)(bb * OO + o0)) * HWSZ + p;
            float* d1 = out + ((size_t)(bb * OO + o0 + 8)) * HWSZ + p;
            float2 v0, v1;
            v0.x = acc[mf][nf][0] + bv0; v0.y = acc[mf][nf][1] + bv0;
            v1.x = acc[mf][nf][2] + bv1; v1.y = acc[mf][nf][3] + bv1;
            *(float2*)d0 = v0;
            *(float2*)d1 = v1;
        }
    }
}

extern "C" void kernel_launch(void* const* d_in, const int* in_sizes, int n_in,
                              void* d_out, int out_size) {
    const float* inp    = (const float*)d_in[0];  // [8,256,64,64]
    const float* offs   = (const float*)d_in[1];  // [8,18,64,64]
    const float* mask   = (const float*)d_in[2];  // [8,9,64,64]
    const float* weight = (const float*)d_in[3];  // [256,256,3,3]
    const float* bias   = (const float*)d_in[4];  // [256]
    float* out = (float*)d_out;                   // [8,256,64,64]

    cudaFuncSetAttribute(dcn_mma9_kernel,
                         cudaFuncAttributeMaxDynamicSharedMemorySize, SMEM_TOTAL);

    prep_wfrag<<<(18 * WF_PER_JT + 255) / 256, 256>>>(weight);
    prep_nhwc<<<dim3(HWSZ / 32, CC / 32, BB), dim3(32, 8)>>>(inp);

    dim3 grid(HWSZ / TP, BB);   // (32, 8) = 256 CTAs
    dcn_mma9_kernel<<<grid, NT, SMEM_TOTAL>>>(offs, mask, bias, out);
}

// round 12
// speedup vs baseline: 1.2377x; 1.2377x over previous
#include <cuda_runtime.h>
#include <cuda_fp16.h>
#include <cstdint>

// Fixed problem shape
#define BB   8
#define CC   256
#define HH   64
#define WWD  64
#define OO   256
#define KKT  9
#define HWSZ 4096

#define TP   128         // pixel tile per CTA
#define NT   512         // 16 warps: 4 M-warps (o) x 4 N-warps (px)
#define NITER 18         // 2 c-chunks of 128 x 9 kpos (kpos innermost)

// ---- smem layout (bytes) ----
#define SM_T    0           // taps: 1152 x 16B = 18432
#define SM_A    18432       // 2 bufs x 65536 (256 o x 128 c fp16, two SW128 half-planes) -> 149504
#define SM_B    149504      // 2 bufs x 32768 (128 px x 128 c fp16, two SW128 half-planes) -> 215040
#define SMEM_TOTAL 215040

// Packed bilinear tap: 4 corner indices + 4 fp16 weights (mask-premultiplied)
struct __align__(16) Tap {
    unsigned short idx[4];
    __half2 w01;
    __half2 w23;
};

// ---- device scratch ----
__device__ __align__(16) __half g_wh[KKT * OO * CC];              // [k][o][c] fp16
__device__ __align__(16) __half g_xn[(size_t)BB * HWSZ * CC];     // NHWC fp16

// ---------------- prep kernels ----------------
__global__ void prep_weight(const float* __restrict__ w) {
    int o = blockIdx.x, k = blockIdx.y, c = threadIdx.x;
    float v = w[((size_t)o * CC + c) * KKT + k];
    g_wh[((size_t)k * OO + o) * CC + c] = __float2half_rn(v);
}

__global__ void prep_nhwc(const float* __restrict__ x) {
    __shared__ float tile[32][33];
    int bb = blockIdx.z, hw0 = blockIdx.x * 32, c0 = blockIdx.y * 32;
    int tx = threadIdx.x, ty = threadIdx.y;
    const float* src = x + (size_t)bb * CC * HWSZ;
    #pragma unroll
    for (int i = 0; i < 32; i += 8)
        tile[ty + i][tx] = src[(size_t)(c0 + ty + i) * HWSZ + hw0 + tx];
    __syncthreads();
    __half* dst = g_xn + (size_t)bb * HWSZ * CC;
    #pragma unroll
    for (int i = 0; i < 32; i += 8)
        dst[(size_t)(hw0 + ty + i) * CC + c0 + tx] = __float2half_rn(tile[tx][ty + i]);
}

// ---------------- helpers ----------------
__device__ __forceinline__ uint32_t s2u(const void* p) {
    uint32_t r;
    asm("{ .reg .u64 t; cvta.to.shared.u64 t, %1; cvt.u32.u64 %0, t; }" : "=r"(r) : "l"(p));
    return r;
}
__device__ __forceinline__ uint32_t sw128(uint32_t off) {
    return off ^ ((off >> 3) & 0x70);
}
__device__ __forceinline__ void bar_named(int id) {
    asm volatile("bar.sync %0, 128;" :: "r"(id) : "memory");
}
__device__ __forceinline__ void ldsm_x4(uint32_t addr, uint32_t& r0, uint32_t& r1,
                                        uint32_t& r2, uint32_t& r3) {
    asm volatile("ldmatrix.sync.aligned.m8n8.x4.shared.b16 {%0,%1,%2,%3}, [%4];"
                 : "=r"(r0), "=r"(r1), "=r"(r2), "=r"(r3) : "r"(addr));
}
__device__ __forceinline__ void mma_fp16(float* d, const uint32_t* a, uint32_t b0, uint32_t b1) {
    asm volatile("mma.sync.aligned.m16n8k16.row.col.f32.f16.f16.f32 "
                 "{%0,%1,%2,%3}, {%4,%5,%6,%7}, {%8,%9}, {%0,%1,%2,%3};"
                 : "+f"(d[0]), "+f"(d[1]), "+f"(d[2]), "+f"(d[3])
                 : "r"(a[0]), "r"(a[1]), "r"(a[2]), "r"(a[3]), "r"(b0), "r"(b1));
}
__device__ __forceinline__ void cp16(uint32_t dst, const void* src) {
    asm volatile("cp.async.cg.shared.global [%0], [%1], 16;" :: "r"(dst), "l"(src) : "memory");
}
__device__ __forceinline__ void cp_commit() { asm volatile("cp.async.commit_group;" ::: "memory"); }
__device__ __forceinline__ void cp_wait0()  { asm volatile("cp.async.wait_group 0;"  ::: "memory"); }

extern __shared__ char smraw[];

__global__ __launch_bounds__(NT, 1)
void dcn_mma10_kernel(const float* __restrict__ offs,
                      const float* __restrict__ mask,
                      const float* __restrict__ bias,
                      float* __restrict__ out) {
    const int tid  = threadIdx.x;
    const int lane = tid & 31;
    const int wid  = tid >> 5;
    const int warpM = wid >> 2;        // 0..3 -> 64 o-rows (A group)
    const int warpN = wid & 3;         // 0..3 -> 32 px     (B group)
    const int bb   = blockIdx.y;
    const int hw0  = blockIdx.x * TP;

    Tap* sT = (Tap*)(smraw + SM_T);
    const uint32_t uA = s2u(smraw + SM_A);
    const uint32_t uB = s2u(smraw + SM_B);

    // ---- taps: bilinear corner indices + mask-premultiplied fp16 weights ----
    for (int i = tid; i < KKT * TP; i += NT) {
        const int k  = i / TP;
        const int p  = i - k * TP;
        const int hw = hw0 + p;
        const int h  = hw >> 6;
        const int w  = hw & 63;

        const float oy = offs[((size_t)bb * 18 + k * 2 + 0) * HWSZ + hw];
        const float ox = offs[((size_t)bb * 18 + k * 2 + 1) * HWSZ + hw];
        const float m  = mask[((size_t)bb * KKT + k) * HWSZ + hw];

        const float py = (float)(h - 1 + k / 3) + oy;
        const float px = (float)(w - 1 + k % 3) + ox;
        const float fy = floorf(py), fx = floorf(px);
        const int y0 = (int)fy, x0 = (int)fx;
        const float ly = py - fy, lx = px - fx;
        const float hy = 1.0f - ly, hx = 1.0f - lx;

        const bool vy0 = (y0 >= 0) && (y0 < HH);
        const bool vy1 = (y0 + 1 >= 0) && (y0 + 1 < HH);
        const bool vx0 = (x0 >= 0) && (x0 < WWD);
        const bool vx1 = (x0 + 1 >= 0) && (x0 + 1 < WWD);
        const int cy0 = min(max(y0, 0), HH - 1);
        const int cy1 = min(max(y0 + 1, 0), HH - 1);
        const int cx0 = min(max(x0, 0), WWD - 1);
        const int cx1 = min(max(x0 + 1, 0), WWD - 1);

        Tap t;
        t.idx[0] = (unsigned short)(cy0 * WWD + cx0);
        t.idx[1] = (unsigned short)(cy0 * WWD + cx1);
        t.idx[2] = (unsigned short)(cy1 * WWD + cx0);
        t.idx[3] = (unsigned short)(cy1 * WWD + cx1);
        const float w0v = (vy0 && vx0) ? hy * hx * m : 0.0f;
        const float w1v = (vy0 && vx1) ? hy * lx * m : 0.0f;
        const float w2v = (vy1 && vx0) ? ly * hx * m : 0.0f;
        const float w3v = (vy1 && vx1) ? ly * lx * m : 0.0f;
        t.w01 = __floats2half2_rn(w0v, w1v);
        t.w23 = __floats2half2_rn(w2v, w3v);
        sT[i] = t;
    }
    __syncthreads();   // taps ready (one full barrier only)

    const __half* __restrict__ xb = g_xn + (size_t)bb * HWSZ * CC;

    float acc[4][4][4];
    #pragma unroll
    for (int mf = 0; mf < 4; ++mf)
        #pragma unroll
        for (int nf = 0; nf < 4; ++nf)
            #pragma unroll
            for (int r = 0; r < 4; ++r) acc[mf][nf][r] = 0.0f;

    // ---- stage A: group-private. A-group m (warps 4m..4m+3) stages its own
    //      64 o-rows [64m, 64m+64) into both SW128 half-planes via cp.async ----
    const int ltA = warpN * 32 + lane;   // 0..127 local id within A group
    auto stageA = [&](int jt, int buf) {
        const int kpos = jt % KKT;
        const int c0   = (jt / KKT) * 128;
        const int q   = ltA & 7;          // 16B chunk within 128B row
        const int r16 = ltA >> 3;         // 0..15
        const uint32_t abase = uA + buf * 65536;
        #pragma unroll
        for (int rr = 0; rr < 4; ++rr) {
            const int row = warpM * 64 + r16 + rr * 16;
            const __half* src = g_wh + ((size_t)kpos * OO + row) * CC + c0 + q * 8;
            const uint32_t swoff = sw128((uint32_t)(row * 128 + q * 16));
            cp16(abase + swoff, src);              // half-plane 0
            cp16(abase + 32768 + swoff, src + 64); // half-plane 1
        }
    };

    // B: group-private. Warp builds 8 px inside its OWN warpN slice:
    //    pp = warpN*32 + warpM*8 + p  (slice n built by its 4 consumers)
    uint2   g[2][4];
    __half2 wA[2], wB[2];
    const int ppBase = warpN * 32 + warpM * 8;
    auto loadP = [&](int jt, int p, int s) {
        const int kpos = jt % KKT;
        const int c0   = (jt / KKT) * 128;
        const __half* xc = xb + c0 + 4 * lane;
        const Tap t = sT[kpos * TP + ppBase + p];   // single LDS.128
        g[s][0] = *(const uint2*)(xc + (size_t)t.idx[0] * CC);
        g[s][1] = *(const uint2*)(xc + (size_t)t.idx[1] * CC);
        g[s][2] = *(const uint2*)(xc + (size_t)t.idx[2] * CC);
        g[s][3] = *(const uint2*)(xc + (size_t)t.idx[3] * CC);
        wA[s] = t.w01;
        wB[s] = t.w23;
    };
    auto storeP = [&](int p, int s, int buf) {
        char* Bb = smraw + SM_B + buf * 32768 + (lane >> 4) * 16384;
        const int pp = ppBase + p;
        const __half2 h0 = __low2half2(wA[s]);
        const __half2 h1 = __high2half2(wA[s]);
        const __half2 h2 = __low2half2(wB[s]);
        const __half2 h3 = __high2half2(wB[s]);
        __half2 vA = __hmul2(h0, *(__half2*)&g[s][0].x);
        vA = __hfma2(h1, *(__half2*)&g[s][1].x, vA);
        vA = __hfma2(h2, *(__half2*)&g[s][2].x, vA);
        vA = __hfma2(h3, *(__half2*)&g[s][3].x, vA);
        __half2 vBv = __hmul2(h0, *(__half2*)&g[s][0].y);
        vBv = __hfma2(h1, *(__half2*)&g[s][1].y, vBv);
        vBv = __hfma2(h2, *(__half2*)&g[s][2].y, vBv);
        vBv = __hfma2(h3, *(__half2*)&g[s][3].y, vBv);
        uint2 pk;
        pk.x = *(uint32_t*)&vA;
        pk.y = *(uint32_t*)&vBv;
        *(uint2*)(Bb + sw128((uint32_t)(pp * 128 + (lane & 15) * 8))) = pk;
    };
    auto mmaKS = [&](int ks, int buf) {
        const int half = ks >> 2;
        const int ksl  = ks & 3;
        const uint32_t abase = uA + buf * 65536 + half * 32768;
        const uint32_t bbase = uB + buf * 32768 + half * 16384;
        uint32_t a[4][4];
        #pragma unroll
        for (int mf = 0; mf < 4; ++mf) {
            const uint32_t off = (uint32_t)((warpM * 64 + mf * 16 + (lane & 15)) * 128
                                            + ksl * 32 + (lane >> 4) * 16);
            ldsm_x4(abase + sw128(off), a[mf][0], a[mf][1], a[mf][2], a[mf][3]);
        }
        uint32_t bfr[4][2];
        #pragma unroll
        for (int pb = 0; pb < 2; ++pb) {
            const uint32_t off = (uint32_t)((warpN * 32 + pb * 16 + (lane & 15)) * 128
                                            + ksl * 32 + (lane >> 4) * 16);
            uint32_t r0, r1, r2, r3;
            ldsm_x4(bbase + sw128(off), r0, r1, r2, r3);
            bfr[pb * 2 + 0][0] = r0; bfr[pb * 2 + 0][1] = r2;
            bfr[pb * 2 + 1][0] = r1; bfr[pb * 2 + 1][1] = r3;
        }
        #pragma unroll
        for (int mf = 0; mf < 4; ++mf)
            #pragma unroll
            for (int nf = 0; nf < 4; ++nf)
                mma_fp16(acc[mf][nf], a[mf], bfr[nf][0], bfr[nf][1]);
    };

    // ---- prologue: build iteration 0 into buffer 0 ----
    stageA(0, 0);
    cp_commit();
    #pragma unroll
    for (int p = 0; p < 8; ++p) { loadP(0, p, p & 1); storeP(p, p & 1, 0); }
    cp_wait0();
    bar_named(5 + warpM);    // A group ready
    bar_named(1 + warpN);    // B group ready

    // ---- main loop: group-local named barriers only ----
    for (int it = 0; it < NITER; ++it) {
        const int buf  = it & 1;
        const int nbuf = buf ^ 1;
        const bool more = (it + 1 < NITER);
        if (more) { stageA(it + 1, nbuf); cp_commit(); }
        if (more) { loadP(it + 1, 0, 0); loadP(it + 1, 1, 1); }

        #pragma unroll
        for (int j = 0; j < 8; ++j) {
            mmaKS(j, buf);
            if (more) {
                storeP(j, j & 1, nbuf);
                if (j < 6) loadP(it + 1, j + 2, j & 1);
            }
        }

        cp_wait0();
        bar_named(5 + warpM);    // my A block (next buf) staged by my group
        bar_named(1 + warpN);    // my B slice (next buf) built by my group
    }

    // ---- epilogue: bias add + fp32 stores ----
    #pragma unroll
    for (int mf = 0; mf < 4; ++mf) {
        const int o0 = warpM * 64 + mf * 16 + (lane >> 2);
        const float bv0 = bias[o0];
        const float bv1 = bias[o0 + 8];
        #pragma unroll
        for (int nf = 0; nf < 4; ++nf) {
            const int p = hw0 + warpN * 32 + nf * 8 + (lane & 3) * 2;
            float* d0 = out + ((size_t)(bb * OO + o0)) * HWSZ + p;
            float* d1 = out + ((size_t)(bb * OO + o0 + 8)) * HWSZ + p;
            float2 v0, v1;
            v0.x = acc[mf][nf][0] + bv0; v0.y = acc[mf][nf][1] + bv0;
            v1.x = acc[mf][nf][2] + bv1; v1.y = acc[mf][nf][3] + bv1;
            *(float2*)d0 = v0;
            *(float2*)d1 = v1;
        }
    }
}

extern "C" void kernel_launch(void* const* d_in, const int* in_sizes, int n_in,
                              void* d_out, int out_size) {
    const float* inp    = (const float*)d_in[0];  // [8,256,64,64]
    const float* offs   = (const float*)d_in[1];  // [8,18,64,64]
    const float* mask   = (const float*)d_in[2];  // [8,9,64,64]
    const float* weight = (const float*)d_in[3];  // [256,256,3,3]
    const float* bias   = (const float*)d_in[4];  // [256]
    float* out = (float*)d_out;                   // [8,256,64,64]

    cudaFuncSetAttribute(dcn_mma10_kernel,
                         cudaFuncAttributeMaxDynamicSharedMemorySize, SMEM_TOTAL);

    prep_weight<<<dim3(OO, KKT), CC>>>(weight);
    prep_nhwc<<<dim3(HWSZ / 32, CC / 32, BB), dim3(32, 8)>>>(inp);

    dim3 grid(HWSZ / TP, BB);   // (32, 8) = 256 CTAs
    dcn_mma10_kernel<<<grid, NT, SMEM_TOTAL>>>(offs, mask, bias, out);
}

// round 13
// speedup vs baseline: 1.2557x; 1.0145x over previous
#include <cuda_runtime.h>
#include <cuda_fp16.h>
#include <cstdint>

// Fixed problem shape
#define BB   8
#define CC   256
#define HH   64
#define WWD  64
#define OO   256
#define KKT  9
#define HWSZ 4096

#define TP   128         // pixel tile per CTA
#define NT   512         // 16 warps: 4 M-warps (o) x 4 N-warps (px)
#define NITER 18         // 2 c-chunks of 128 x 9 kpos (kpos innermost)

// ---- smem layout (bytes) ----
#define SM_T    0           // taps: 1152 x 16B = 18432
#define SM_A    18432       // 2 bufs x 65536 (256 o x 128 c fp16, two SW128 half-planes)
#define SM_B    149504      // 2 bufs x 32768 (128 px x 128 c fp16, two SW128 half-planes)
#define SMEM_TOTAL 215040

// Packed bilinear tap: 4 corner indices + 4 fp16 weights (mask-premultiplied)
struct __align__(16) Tap {
    unsigned short idx[4];
    __half2 w01;
    __half2 w23;
};

// ---- device scratch ----
__device__ __align__(16) __half g_wh[KKT * OO * CC];              // [k][o][c] fp16
__device__ __align__(16) __half g_xn[(size_t)BB * HWSZ * CC];     // NHWC fp16

// ---------------- merged prep kernel (ONE launch: weights + NHWC transpose) ----------------
// blocks [0, 2304): weight fp32->fp16 relayout  [k][o][c]
// blocks [2304, 2304+8192): NCHW -> NHWC fp16 transpose (32x32 tiles)
#define PREP_WBLK 2304
#define PREP_XBLK 8192
__global__ void prep_all(const float* __restrict__ w, const float* __restrict__ x) {
    __shared__ float tile[32][33];
    if (blockIdx.x < PREP_WBLK) {
        const int o = blockIdx.x & 255;
        const int k = blockIdx.x >> 8;
        const int c = threadIdx.x;
        float v = w[((size_t)o * CC + c) * KKT + k];
        g_wh[((size_t)k * OO + o) * CC + c] = __float2half_rn(v);
    } else {
        const int bidx = blockIdx.x - PREP_WBLK;
        const int bb  = bidx >> 10;                 // 1024 blocks per batch
        const int rem = bidx & 1023;
        const int hw0 = (rem & 127) * 32;           // 128 hw-tiles
        const int c0  = (rem >> 7) * 32;            // 8 c-tiles
        const int tx = threadIdx.x & 31;
        const int ty = threadIdx.x >> 5;            // 0..7
        const float* src = x + (size_t)bb * CC * HWSZ;
        #pragma unroll
        for (int i = 0; i < 32; i += 8)
            tile[ty + i][tx] = src[(size_t)(c0 + ty + i) * HWSZ + hw0 + tx];
        __syncthreads();
        __half* dst = g_xn + (size_t)bb * HWSZ * CC;
        #pragma unroll
        for (int i = 0; i < 32; i += 8)
            dst[(size_t)(hw0 + ty + i) * CC + c0 + tx] = __float2half_rn(tile[tx][ty + i]);
    }
}

// ---------------- helpers ----------------
__device__ __forceinline__ uint32_t s2u(const void* p) {
    uint32_t r;
    asm("{ .reg .u64 t; cvta.to.shared.u64 t, %1; cvt.u32.u64 %0, t; }" : "=r"(r) : "l"(p));
    return r;
}
__device__ __forceinline__ uint32_t sw128(uint32_t off) {
    return off ^ ((off >> 3) & 0x70);
}
__device__ __forceinline__ void ldsm_x4(uint32_t addr, uint32_t& r0, uint32_t& r1,
                                        uint32_t& r2, uint32_t& r3) {
    asm volatile("ldmatrix.sync.aligned.m8n8.x4.shared.b16 {%0,%1,%2,%3}, [%4];"
                 : "=r"(r0), "=r"(r1), "=r"(r2), "=r"(r3) : "r"(addr));
}
__device__ __forceinline__ void mma_fp16(float* d, const uint32_t* a, uint32_t b0, uint32_t b1) {
    asm volatile("mma.sync.aligned.m16n8k16.row.col.f32.f16.f16.f32 "
                 "{%0,%1,%2,%3}, {%4,%5,%6,%7}, {%8,%9}, {%0,%1,%2,%3};"
                 : "+f"(d[0]), "+f"(d[1]), "+f"(d[2]), "+f"(d[3])
                 : "r"(a[0]), "r"(a[1]), "r"(a[2]), "r"(a[3]), "r"(b0), "r"(b1));
}
__device__ __forceinline__ void cp16(uint32_t dst, const void* src) {
    asm volatile("cp.async.cg.shared.global [%0], [%1], 16;" :: "r"(dst), "l"(src) : "memory");
}
__device__ __forceinline__ void cp_commit() { asm volatile("cp.async.commit_group;" ::: "memory"); }
__device__ __forceinline__ void cp_wait0()  { asm volatile("cp.async.wait_group 0;"  ::: "memory"); }

extern __shared__ char smraw[];

__global__ __launch_bounds__(NT, 1)
void dcn_mma11_kernel(const float* __restrict__ offs,
                      const float* __restrict__ mask,
                      const float* __restrict__ bias,
                      float* __restrict__ out) {
    const int tid  = threadIdx.x;
    const int lane = tid & 31;
    const int wid  = tid >> 5;
    const int warpM = wid >> 2;        // 0..3 -> 64 o-rows
    const int warpN = wid & 3;         // 0..3 -> 32 px
    const int bb   = blockIdx.y;
    const int hw0  = blockIdx.x * TP;

    Tap* sT = (Tap*)(smraw + SM_T);
    const uint32_t uA = s2u(smraw + SM_A);
    const uint32_t uB = s2u(smraw + SM_B);

    // ---- taps: bilinear corner indices + mask-premultiplied fp16 weights ----
    for (int i = tid; i < KKT * TP; i += NT) {
        const int k  = i / TP;
        const int p  = i - k * TP;
        const int hw = hw0 + p;
        const int h  = hw >> 6;
        const int w  = hw & 63;

        const float oy = offs[((size_t)bb * 18 + k * 2 + 0) * HWSZ + hw];
        const float ox = offs[((size_t)bb * 18 + k * 2 + 1) * HWSZ + hw];
        const float m  = mask[((size_t)bb * KKT + k) * HWSZ + hw];

        const float py = (float)(h - 1 + k / 3) + oy;
        const float px = (float)(w - 1 + k % 3) + ox;
        const float fy = floorf(py), fx = floorf(px);
        const int y0 = (int)fy, x0 = (int)fx;
        const float ly = py - fy, lx = px - fx;
        const float hy = 1.0f - ly, hx = 1.0f - lx;

        const bool vy0 = (y0 >= 0) && (y0 < HH);
        const bool vy1 = (y0 + 1 >= 0) && (y0 + 1 < HH);
        const bool vx0 = (x0 >= 0) && (x0 < WWD);
        const bool vx1 = (x0 + 1 >= 0) && (x0 + 1 < WWD);
        const int cy0 = min(max(y0, 0), HH - 1);
        const int cy1 = min(max(y0 + 1, 0), HH - 1);
        const int cx0 = min(max(x0, 0), WWD - 1);
        const int cx1 = min(max(x0 + 1, 0), WWD - 1);

        Tap t;
        t.idx[0] = (unsigned short)(cy0 * WWD + cx0);
        t.idx[1] = (unsigned short)(cy0 * WWD + cx1);
        t.idx[2] = (unsigned short)(cy1 * WWD + cx0);
        t.idx[3] = (unsigned short)(cy1 * WWD + cx1);
        const float w0v = (vy0 && vx0) ? hy * hx * m : 0.0f;
        const float w1v = (vy0 && vx1) ? hy * lx * m : 0.0f;
        const float w2v = (vy1 && vx0) ? ly * hx * m : 0.0f;
        const float w3v = (vy1 && vx1) ? ly * lx * m : 0.0f;
        t.w01 = __floats2half2_rn(w0v, w1v);
        t.w23 = __floats2half2_rn(w2v, w3v);
        sT[i] = t;
    }
    __syncthreads();

    const __half* __restrict__ xb = g_xn + (size_t)bb * HWSZ * CC;

    float acc[4][4][4];
    #pragma unroll
    for (int mf = 0; mf < 4; ++mf)
        #pragma unroll
        for (int nf = 0; nf < 4; ++nf)
            #pragma unroll
            for (int r = 0; r < 4; ++r) acc[mf][nf][r] = 0.0f;

    // ---- stage A: 256 o x 128 c fp16 as two SW128 half-planes, via cp.async ----
    auto stageA = [&](int jt, int buf) {
        const int kpos = jt % KKT;
        const int c0   = (jt / KKT) * 128;
        const int q = tid & 7;          // 16B chunk within 128B row
        const int r = tid >> 3;         // 0..63
        const uint32_t abase = uA + buf * 65536;
        const uint32_t swoff = sw128((uint32_t)(r * 128 + q * 16));
        #pragma unroll
        for (int rr = 0; rr < 4; ++rr) {
            const int row = r + rr * 64;
            const __half* src = g_wh + ((size_t)kpos * OO + row) * CC + c0 + q * 8;
            cp16(abase + swoff + rr * 64 * 128, src);              // half-plane 0
            cp16(abase + 32768 + swoff + rr * 64 * 128, src + 64); // half-plane 1
        }
    };

    // Per-pixel gather pipeline: 2 slots x (4 corners uint2 + packed weights)
    uint2   g[2][4];
    __half2 wA[2], wB[2];
    auto loadP = [&](int jt, int p, int s) {
        const int kpos = jt % KKT;
        const int c0   = (jt / KKT) * 128;
        const __half* xc = xb + c0 + 4 * lane;
        const Tap t = sT[kpos * TP + wid * 8 + p];   // single LDS.128
        g[s][0] = *(const uint2*)(xc + (size_t)t.idx[0] * CC);
        g[s][1] = *(const uint2*)(xc + (size_t)t.idx[1] * CC);
        g[s][2] = *(const uint2*)(xc + (size_t)t.idx[2] * CC);
        g[s][3] = *(const uint2*)(xc + (size_t)t.idx[3] * CC);
        wA[s] = t.w01;
        wB[s] = t.w23;
    };
    auto storeP = [&](int p, int s, int buf) {
        char* Bb = smraw + SM_B + buf * 32768 + (lane >> 4) * 16384;
        const int pp = wid * 8 + p;
        const __half2 h0 = __low2half2(wA[s]);
        const __half2 h1 = __high2half2(wA[s]);
        const __half2 h2 = __low2half2(wB[s]);
        const __half2 h3 = __high2half2(wB[s]);
        __half2 vA = __hmul2(h0, *(__half2*)&g[s][0].x);
        vA = __hfma2(h1, *(__half2*)&g[s][1].x, vA);
        vA = __hfma2(h2, *(__half2*)&g[s][2].x, vA);
        vA = __hfma2(h3, *(__half2*)&g[s][3].x, vA);
        __half2 vBv = __hmul2(h0, *(__half2*)&g[s][0].y);
        vBv = __hfma2(h1, *(__half2*)&g[s][1].y, vBv);
        vBv = __hfma2(h2, *(__half2*)&g[s][2].y, vBv);
        vBv = __hfma2(h3, *(__half2*)&g[s][3].y, vBv);
        uint2 pk;
        pk.x = *(uint32_t*)&vA;
        pk.y = *(uint32_t*)&vBv;
        *(uint2*)(Bb + sw128((uint32_t)(pp * 128 + (lane & 15) * 8))) = pk;
    };
    auto mmaKS = [&](int ks, int buf) {
        const int half = ks >> 2;
        const int ksl  = ks & 3;
        const uint32_t abase = uA + buf * 65536 + half * 32768;
        const uint32_t bbase = uB + buf * 32768 + half * 16384;
        uint32_t a[4][4];
        #pragma unroll
        for (int mf = 0; mf < 4; ++mf) {
            const uint32_t off = (uint32_t)((warpM * 64 + mf * 16 + (lane & 15)) * 128
                                            + ksl * 32 + (lane >> 4) * 16);
            ldsm_x4(abase + sw128(off), a[mf][0], a[mf][1], a[mf][2], a[mf][3]);
        }
        uint32_t bfr[4][2];
        #pragma unroll
        for (int pb = 0; pb < 2; ++pb) {
            const uint32_t off = (uint32_t)((warpN * 32 + pb * 16 + (lane & 15)) * 128
                                            + ksl * 32 + (lane >> 4) * 16);
            uint32_t r0, r1, r2, r3;
            ldsm_x4(bbase + sw128(off), r0, r1, r2, r3);
            bfr[pb * 2 + 0][0] = r0; bfr[pb * 2 + 0][1] = r2;
            bfr[pb * 2 + 1][0] = r1; bfr[pb * 2 + 1][1] = r3;
        }
        #pragma unroll
        for (int mf = 0; mf < 4; ++mf)
            #pragma unroll
            for (int nf = 0; nf < 4; ++nf)
                mma_fp16(acc[mf][nf], a[mf], bfr[nf][0], bfr[nf][1]);
    };

    // ---- prologue: build iteration 0 into buffer 0 ----
    stageA(0, 0);
    cp_commit();
    #pragma unroll
    for (int p = 0; p < 8; ++p) { loadP(0, p, p & 1); storeP(p, p & 1, 0); }
    cp_wait0();
    __syncthreads();

    // ---- main loop: one sync per iter; build(it+1) woven into the 8 mmaKS of it ----
    for (int it = 0; it < NITER; ++it) {
        const int buf  = it & 1;
        const int nbuf = buf ^ 1;
        const bool more = (it + 1 < NITER);
        if (more) { stageA(it + 1, nbuf); cp_commit(); }
        if (more) { loadP(it + 1, 0, 0); loadP(it + 1, 1, 1); }

        #pragma unroll
        for (int j = 0; j < 8; ++j) {
            mmaKS(j, buf);
            if (more) {
                storeP(j, j & 1, nbuf);
                if (j < 6) loadP(it + 1, j + 2, j & 1);
            }
        }

        cp_wait0();
        __syncthreads();
    }

    // ---- epilogue: bias add + fp32 stores ----
    #pragma unroll
    for (int mf = 0; mf < 4; ++mf) {
        const int o0 = warpM * 64 + mf * 16 + (lane >> 2);
        const float bv0 = bias[o0];
        const float bv1 = bias[o0 + 8];
        #pragma unroll
        for (int nf = 0; nf < 4; ++nf) {
            const int p = hw0 + warpN * 32 + nf * 8 + (lane & 3) * 2;
            float* d0 = out + ((size_t)(bb * OO + o0)) * HWSZ + p;
            float* d1 = out + ((size_t)(bb * OO + o0 + 8)) * HWSZ + p;
            float2 v0, v1;
            v0.x = acc[mf][nf][0] + bv0; v0.y = acc[mf][nf][1] + bv0;
            v1.x = acc[mf][nf][2] + bv1; v1.y = acc[mf][nf][3] + bv1;
            *(float2*)d0 = v0;
            *(float2*)d1 = v1;
        }
    }
}

extern "C" void kernel_launch(void* const* d_in, const int* in_sizes, int n_in,
                              void* d_out, int out_size) {
    const float* inp    = (const float*)d_in[0];  // [8,256,64,64]
    const float* offs   = (const float*)d_in[1];  // [8,18,64,64]
    const float* mask   = (const float*)d_in[2];  // [8,9,64,64]
    const float* weight = (const float*)d_in[3];  // [256,256,3,3]
    const float* bias   = (const float*)d_in[4];  // [256]
    float* out = (float*)d_out;                   // [8,256,64,64]

    cudaFuncSetAttribute(dcn_mma11_kernel,
                         cudaFuncAttributeMaxDynamicSharedMemorySize, SMEM_TOTAL);

    prep_all<<<PREP_WBLK + PREP_XBLK, 256>>>(weight, inp);

    dim3 grid(HWSZ / TP, BB);   // (32, 8) = 256 CTAs
    dcn_mma11_kernel<<<grid, NT, SMEM_TOTAL>>>(offs, mask, bias, out);
}